// round 1
// baseline (speedup 1.0000x reference)
#include <cuda_runtime.h>
#include <cuda_bf16.h>

#define D 128
#define D4 (D / 4)          // 32 float4 per row
#define THREADS 512
#define RG (THREADS / D4)   // 16 row-groups

__global__ __launch_bounds__(THREADS, 4)
void graphnorm_kernel(const float* __restrict__ x,
                      const float* __restrict__ gamma,
                      const float* __restrict__ beta,
                      const int* __restrict__ batch,
                      float* __restrict__ out)
{
    const int g   = blockIdx.x;
    const int c4  = threadIdx.x & (D4 - 1);   // column quad 0..31
    const int rg  = threadIdx.x >> 5;         // row group 0..15

    const int start = batch[g];
    const int end   = batch[g + 1];
    const float cnt = (float)(end - start);

    const float4* __restrict__ xv = (const float4*)x;
    float4* __restrict__ ov = (float4*)out;

    // ---- pass 1: per-thread partial sum / sumsq over strided rows ----
    float4 s = make_float4(0.f, 0.f, 0.f, 0.f);
    float4 q = make_float4(0.f, 0.f, 0.f, 0.f);
    for (int r = start + rg; r < end; r += RG) {
        float4 v = xv[(long)r * D4 + c4];
        s.x += v.x; s.y += v.y; s.z += v.z; s.w += v.w;
        q.x += v.x * v.x; q.y += v.y * v.y; q.z += v.z * v.z; q.w += v.w * v.w;
    }

    __shared__ float4 ssum[RG][D4];
    __shared__ float4 ssq [RG][D4];
    __shared__ float4 smean[D4];
    __shared__ float4 sinv [D4];

    ssum[rg][c4] = s;
    ssq [rg][c4] = q;
    __syncthreads();

    // ---- cross-warp reduce + stats (warp 0: one lane per column quad) ----
    if (rg == 0) {
        float4 ts = ssum[0][c4];
        float4 tq = ssq [0][c4];
        #pragma unroll
        for (int i = 1; i < RG; i++) {
            float4 a = ssum[i][c4];
            float4 b = ssq [i][c4];
            ts.x += a.x; ts.y += a.y; ts.z += a.z; ts.w += a.w;
            tq.x += b.x; tq.y += b.y; tq.z += b.z; tq.w += b.w;
        }
        float4 m, iv;
        m.x = ts.x / cnt; m.y = ts.y / cnt; m.z = ts.z / cnt; m.w = ts.w / cnt;
        float denom = cnt - 1.0f;
        // unbiased var, then 1/(std + eps)
        iv.x = 1.0f / (sqrtf(fmaxf((tq.x - cnt * m.x * m.x) / denom, 0.f)) + 1e-5f);
        iv.y = 1.0f / (sqrtf(fmaxf((tq.y - cnt * m.y * m.y) / denom, 0.f)) + 1e-5f);
        iv.z = 1.0f / (sqrtf(fmaxf((tq.z - cnt * m.z * m.z) / denom, 0.f)) + 1e-5f);
        iv.w = 1.0f / (sqrtf(fmaxf((tq.w - cnt * m.w * m.w) / denom, 0.f)) + 1e-5f);
        smean[c4] = m;
        sinv [c4] = iv;
    }
    __syncthreads();

    // ---- pass 2: normalize (x re-read should be mostly L2 hits) ----
    const float4 g4 = ((const float4*)gamma)[c4];
    const float4 b4 = ((const float4*)beta)[c4];
    const float4 m  = smean[c4];
    const float4 iv = sinv [c4];

    for (int r = start + rg; r < end; r += RG) {
        float4 v = xv[(long)r * D4 + c4];
        float4 o;
        o.x = g4.x * (v.x - m.x) * iv.x + b4.x;
        o.y = g4.y * (v.y - m.y) * iv.y + b4.y;
        o.z = g4.z * (v.z - m.z) * iv.z + b4.z;
        o.w = g4.w * (v.w - m.w) * iv.w + b4.w;
        ov[(long)r * D4 + c4] = o;
    }
}

extern "C" void kernel_launch(void* const* d_in, const int* in_sizes, int n_in,
                              void* d_out, int out_size)
{
    const float* x     = (const float*)d_in[0];
    const float* gamma = (const float*)d_in[1];
    const float* beta  = (const float*)d_in[2];
    const int*   batch = (const int*)d_in[3];
    float* out = (float*)d_out;

    const int G = in_sizes[3] - 1;   // number of segments
    graphnorm_kernel<<<G, THREADS>>>(x, gamma, beta, batch, out);
}

// round 2
// speedup vs baseline: 1.2046x; 1.2046x over previous
#include <cuda_runtime.h>
#include <cuda_bf16.h>

#define D4 32               // float4 per full row (D=128)
#define QPC 8               // float4-quads per CTA  (32 columns)
#define THREADS 1024
#define RB (THREADS / QPC)  // 128 distinct row-bases
#define RITER 8             // covers up to 1024 rows per graph
#define MAXROWS 1024

__global__ __launch_bounds__(THREADS, 1)
void graphnorm_1pass(const float* __restrict__ x,
                     const float* __restrict__ gamma,
                     const float* __restrict__ beta,
                     const int* __restrict__ batch,
                     float* __restrict__ out)
{
    extern __shared__ float4 tile[];                 // [MAXROWS][QPC] = 128 KB
    __shared__ float4 psum[THREADS / 32][QPC];
    __shared__ float4 psq [THREADS / 32][QPC];
    __shared__ float4 smean[QPC], sinv[QPC];

    const int g    = blockIdx.x;
    const int cb   = blockIdx.y;                     // column block 0..3
    const int quad = threadIdx.x & (QPC - 1);        // 0..7
    const int rb   = threadIdx.x >> 3;               // 0..127
    const int warp = threadIdx.x >> 5;
    const int lane = threadIdx.x & 31;

    const int start = batch[g];
    const int end   = batch[g + 1];
    const int cnt   = end - start;
    const float fcnt = (float)cnt;

    const float4* __restrict__ xv = (const float4*)x;
    float4* __restrict__ ov = (float4*)out;
    const long colq = (long)cb * QPC + quad;         // float4 column index 0..31

    // ---- single load pass: gmem -> regs (accumulate) -> smem tile ----
    float4 s = make_float4(0.f, 0.f, 0.f, 0.f);
    float4 q = make_float4(0.f, 0.f, 0.f, 0.f);
    #pragma unroll
    for (int i = 0; i < RITER; i++) {
        int r = rb + i * RB;
        if (r < cnt) {
            float4 v = xv[(long)(start + r) * D4 + colq];
            tile[r * QPC + quad] = v;
            s.x += v.x; s.y += v.y; s.z += v.z; s.w += v.w;
            q.x += v.x * v.x; q.y += v.y * v.y; q.z += v.z * v.z; q.w += v.w * v.w;
        }
    }

    // ---- warp reduce: lanes {quad, quad+8, quad+16, quad+24} share a column ----
    #pragma unroll
    for (int off = 8; off <= 16; off <<= 1) {
        s.x += __shfl_xor_sync(0xffffffffu, s.x, off);
        s.y += __shfl_xor_sync(0xffffffffu, s.y, off);
        s.z += __shfl_xor_sync(0xffffffffu, s.z, off);
        s.w += __shfl_xor_sync(0xffffffffu, s.w, off);
        q.x += __shfl_xor_sync(0xffffffffu, q.x, off);
        q.y += __shfl_xor_sync(0xffffffffu, q.y, off);
        q.z += __shfl_xor_sync(0xffffffffu, q.z, off);
        q.w += __shfl_xor_sync(0xffffffffu, q.w, off);
    }
    if (lane < QPC) { psum[warp][quad] = s; psq[warp][quad] = q; }
    __syncthreads();

    // ---- final reduce across 32 warps + stats (8 threads, one per quad) ----
    if (threadIdx.x < QPC) {
        float4 ts = make_float4(0.f, 0.f, 0.f, 0.f);
        float4 tq = make_float4(0.f, 0.f, 0.f, 0.f);
        #pragma unroll
        for (int w = 0; w < THREADS / 32; w++) {
            float4 a = psum[w][threadIdx.x];
            float4 b = psq [w][threadIdx.x];
            ts.x += a.x; ts.y += a.y; ts.z += a.z; ts.w += a.w;
            tq.x += b.x; tq.y += b.y; tq.z += b.z; tq.w += b.w;
        }
        float4 m, iv;
        m.x = ts.x / fcnt; m.y = ts.y / fcnt; m.z = ts.z / fcnt; m.w = ts.w / fcnt;
        float denom = fcnt - 1.0f;
        iv.x = 1.0f / (sqrtf(fmaxf((tq.x - fcnt * m.x * m.x) / denom, 0.f)) + 1e-5f);
        iv.y = 1.0f / (sqrtf(fmaxf((tq.y - fcnt * m.y * m.y) / denom, 0.f)) + 1e-5f);
        iv.z = 1.0f / (sqrtf(fmaxf((tq.z - fcnt * m.z * m.z) / denom, 0.f)) + 1e-5f);
        iv.w = 1.0f / (sqrtf(fmaxf((tq.w - fcnt * m.w * m.w) / denom, 0.f)) + 1e-5f);
        smean[threadIdx.x] = m;
        sinv [threadIdx.x] = iv;
    }
    __syncthreads();

    // ---- normalize from smem, write out (no second DRAM read of x) ----
    const float4 g4 = ((const float4*)gamma)[colq];
    const float4 b4 = ((const float4*)beta)[colq];
    const float4 m  = smean[quad];
    const float4 iv = sinv [quad];

    #pragma unroll
    for (int i = 0; i < RITER; i++) {
        int r = rb + i * RB;
        if (r < cnt) {
            float4 v = tile[r * QPC + quad];
            float4 o;
            o.x = g4.x * (v.x - m.x) * iv.x + b4.x;
            o.y = g4.y * (v.y - m.y) * iv.y + b4.y;
            o.z = g4.z * (v.z - m.z) * iv.z + b4.z;
            o.w = g4.w * (v.w - m.w) * iv.w + b4.w;
            ov[(long)(start + r) * D4 + colq] = o;
        }
    }
}

extern "C" void kernel_launch(void* const* d_in, const int* in_sizes, int n_in,
                              void* d_out, int out_size)
{
    const float* x     = (const float*)d_in[0];
    const float* gamma = (const float*)d_in[1];
    const float* beta  = (const float*)d_in[2];
    const int*   batch = (const int*)d_in[3];
    float* out = (float*)d_out;

    const int G = in_sizes[3] - 1;
    const size_t smem = (size_t)MAXROWS * QPC * sizeof(float4);   // 128 KB

    cudaFuncSetAttribute(graphnorm_1pass,
                         cudaFuncAttributeMaxDynamicSharedMemorySize, (int)smem);

    dim3 grid(G, 4);
    graphnorm_1pass<<<grid, THREADS, smem>>>(x, gamma, beta, batch, out);
}